// round 6
// baseline (speedup 1.0000x reference)
#include <cuda_runtime.h>
#include <cuda_fp16.h>
#include <math.h>

#define NE    30      // electrons
#define NA    10      // atoms
#define NN    40      // en-graph nodes
#define FEAT  64
#define NPE   435     // ee unique pairs
#define NPN   300     // en unique pairs
#define NL    2
#define T_TAB 4096
#define INV_STEP 256.0f   // T_TAB / 16.0 range
#define BLK   512
#define NWARP (BLK / 32)

typedef unsigned long long u64;

__device__ float g_tab_ee[T_TAB * FEAT];
__device__ float g_tab_en[T_TAB * FEAT];

// ---- packed f32x2 helpers (Blackwell) -------------------------------------
__device__ __forceinline__ u64 pack2(float x, float y) {
    u64 r; asm("mov.b64 %0, {%1,%2};" : "=l"(r) : "f"(x), "f"(y)); return r;
}
__device__ __forceinline__ float2 unpack2(u64 v) {
    float2 f; asm("mov.b64 {%0,%1}, %2;" : "=f"(f.x), "=f"(f.y) : "l"(v)); return f;
}
#define FMA2(d, a, b, c) asm("fma.rn.f32x2 %0, %1, %2, %3;" : "=l"(d) : "l"(a), "l"(b), "l"(c))
#define ADD2(d, a, b)    asm("add.rn.f32x2 %0, %1, %2;"     : "=l"(d) : "l"(a), "l"(b))

__device__ __forceinline__ float tanh_fast(float x) {
    float cx = fminf(fmaxf(x, -15.f), 15.f);
    float e = __expf(2.f * cx);
    return __fdividef(e - 1.f, e + 1.f);
}

// ---------------------------------------------------------------------------
// Table build: grid (T_TAB/8, 2), block 256.
// ---------------------------------------------------------------------------
__global__ void build_tab_kernel(const float* __restrict__ wf_ee,
                                 const float* __restrict__ bf_ee,
                                 const float* __restrict__ wf_en,
                                 const float* __restrict__ bf_en) {
    __shared__ float s_wf[FEAT * FEAT];
    __shared__ float s_rbf[8][FEAT];
    const float* wf = blockIdx.y ? wf_en : wf_ee;
    const float* bf = blockIdx.y ? bf_en : bf_ee;
    float* tab      = blockIdx.y ? g_tab_en : g_tab_ee;

    const int t = threadIdx.x;
    for (int i = t; i < FEAT * FEAT; i += 256) s_wf[i] = wf[i];

    const int f  = t & 63;
    const int rg = t >> 6;
    const int base = blockIdx.x * 8;

    #pragma unroll
    for (int rr = 0; rr < 2; rr++) {
        int r = rg + rr * 4;
        float d = (float)(base + r) * (1.0f / INV_STEP);
        float x = d - (float)f * (8.0f / 63.0f);
        s_rbf[r][f] = __expf(-x * x);
    }
    __syncthreads();

    float bfv = bf[f];
    float a0 = bfv, a1 = bfv;
    const int r0 = rg, r1 = rg + 4;
    #pragma unroll
    for (int k = 0; k < FEAT; k++) {
        float w = s_wf[k * FEAT + f];
        a0 = fmaf(s_rbf[r0][k], w, a0);
        a1 = fmaf(s_rbf[r1][k], w, a1);
    }
    tab[(base + r0) * FEAT + f] = tanhf(a0);
    tab[(base + r1) * FEAT + f] = tanhf(a1);
}

// ---------------------------------------------------------------------------
struct __align__(16) Smem {
    __half2 filt2[NPE * 32];      // 55,680 B (en uses first 300*32)
    float   h[NN * FEAT];         // 10,240 (updated in place)
    float   agg[NN * FEAT];       // 10,240 (also distance scratch)
    float4  wlT[NL * 32 * 32];    // 32,768: [l][kk][fp]
    float   bl[NL * FEAT];        // 512
    float   wr[FEAT];             // 256
    float   xyz[NE * 3];          // 360
    float   atm[NA * 3];          // 120
    float   red[NWARP];           // 64
};                                 // ~110,240 B -> 2 CTAs/SM

__device__ __forceinline__ float block_reduce(float v, float* s_red, int t) {
    #pragma unroll
    for (int o = 16; o; o >>= 1) v += __shfl_down_sync(0xffffffffu, v, o);
    if ((t & 31) == 0) s_red[t >> 5] = v;
    __syncthreads();
    if (t == 0) {
        float x = 0.f;
        #pragma unroll
        for (int w = 0; w < NWARP; w++) x += s_red[w];
        s_red[0] = x;
    }
    __syncthreads();
    float r = s_red[0];
    __syncthreads();
    return r;
}

__device__ __forceinline__ void stage_weights(Smem& S, const float* wl,
                                              const float* bl, const float* wr, int t) {
    for (int idx = t; idx < NL * 32 * 32; idx += BLK) {
        int l = idx >> 10, r = idx & 1023;
        int kk = r >> 5, fp = r & 31;
        const float* s0 = &wl[(l * FEAT + 2 * kk) * FEAT + 2 * fp];
        float4 v;
        v.x = s0[0]; v.y = s0[1];
        v.z = s0[FEAT]; v.w = s0[FEAT + 1];
        S.wlT[idx] = v;
    }
    for (int i = t; i < NL * FEAT; i += BLK) S.bl[i] = bl[i];
    if (t < FEAT) S.wr[t] = wr[t];
}

// linear for up to 3 contiguous nodes [node0, node0+cnt):
// h[n] += tanh(agg[n] @ wl + bl), in place.
__device__ __forceinline__ void linearN(Smem& S, int l, int node0, int cnt, int fp) {
    u64 bias = *(const u64*)&S.bl[l * FEAT + 2 * fp];
    u64 ca[3], cb[3];
    #pragma unroll
    for (int s = 0; s < 3; s++) { ca[s] = bias; cb[s] = 0; }
    const float4* wT = &S.wlT[l * 1024 + fp];
    #pragma unroll
    for (int kk = 0; kk < 32; kk += 2) {
        float4 w0 = wT[kk * 32];
        float4 w1 = wT[(kk + 1) * 32];
        u64 w0a = pack2(w0.x, w0.y), w0b = pack2(w0.z, w0.w);
        u64 w1a = pack2(w1.x, w1.y), w1b = pack2(w1.z, w1.w);
        #pragma unroll
        for (int s = 0; s < 3; s++) {
            if (s < cnt) {
                float4 av = *(const float4*)&S.agg[(node0 + s) * FEAT + 2 * kk];
                u64 d;
                d = pack2(av.x, av.x); FMA2(ca[s], d, w0a, ca[s]);
                d = pack2(av.y, av.y); FMA2(cb[s], d, w0b, cb[s]);
                d = pack2(av.z, av.z); FMA2(ca[s], d, w1a, ca[s]);
                d = pack2(av.w, av.w); FMA2(cb[s], d, w1b, cb[s]);
            }
        }
    }
    #pragma unroll
    for (int s = 0; s < 3; s++) {
        if (s < cnt) {
            int n = node0 + s;
            ADD2(ca[s], ca[s], cb[s]);
            float2 sv = unpack2(ca[s]);
            float2 hv = unpack2(*(const u64*)&S.h[n * FEAT + 2 * fp]);
            hv.x += tanh_fast(sv.x);
            hv.y += tanh_fast(sv.y);
            *(u64*)&S.h[n * FEAT + 2 * fp] = pack2(hv.x, hv.y);
        }
    }
}

// en work assignment: warps 0-7 -> 3 electrons, 8-10 -> 2 electrons,
// 11-15 -> 2 atoms. Returns h-space node0.
__device__ __forceinline__ void en_map(int warp, int& node0, int& cnt, bool& isatom) {
    if (warp < 8)       { node0 = 3 * warp;              cnt = 3; isatom = false; }
    else if (warp < 11) { node0 = 24 + 2 * (warp - 8);   cnt = 2; isatom = false; }
    else                { node0 = NE + 2 * (warp - 11);  cnt = 2; isatom = true; }
}

__global__ void __launch_bounds__(BLK, 2) jastrow_kernel(
    const float* __restrict__ pos,    const float* __restrict__ atoms,
    const float* __restrict__ emb_ee, const float* __restrict__ wl_ee,
    const float* __restrict__ bl_ee,  const float* __restrict__ wr_ee,
    const float* __restrict__ br_ee,
    const float* __restrict__ emb_en, const float* __restrict__ wl_en,
    const float* __restrict__ bl_en,  const float* __restrict__ wr_en,
    const float* __restrict__ br_en,
    float* __restrict__ out) {
    extern __shared__ char smem_raw[];
    Smem& S = *reinterpret_cast<Smem*>(smem_raw);
    float* Sd = S.agg;   // distance scratch (dead once filt2 is built)
    const int t = threadIdx.x;
    const int b = blockIdx.x;
    const int warp = t >> 5;
    const int fp = t & 31;

    for (int i = t; i < NE * 3; i += BLK) S.xyz[i] = pos[b * NE * 3 + i];
    for (int i = t; i < NA * 3; i += BLK) S.atm[i] = atoms[i];
    stage_weights(S, wl_ee, bl_ee, wr_ee, t);
    __syncthreads();

    // ================= EE graph =================
    for (int x = t; x < NE * NE; x += BLK) {
        int i = x / NE, j = x % NE;
        if (i < j) {
            int p = ((i * (2 * NE - 1 - i)) >> 1) + j - i - 1;
            float dx = S.xyz[i * 3 + 0] - S.xyz[j * 3 + 0];
            float dy = S.xyz[i * 3 + 1] - S.xyz[j * 3 + 1];
            float dz = S.xyz[i * 3 + 2] - S.xyz[j * 3 + 2];
            Sd[p] = sqrtf(dx * dx + dy * dy + dz * dz);
        }
    }
    __syncthreads();

    for (int it = t; it < NPE * 32; it += BLK) {
        int p = it >> 5, f2 = it & 31;
        float u = fminf(Sd[p] * INV_STEP, (float)(T_TAB - 2) + 0.999f);
        int idx = (int)u;
        float w = u - (float)idx;
        float2 v0 = *(const float2*)&g_tab_ee[idx * FEAT + 2 * f2];
        float2 v1 = *(const float2*)&g_tab_ee[(idx + 1) * FEAT + 2 * f2];
        S.filt2[it] = __floats2half2_rn(fmaf(w, v1.x - v0.x, v0.x),
                                        fmaf(w, v1.y - v0.y, v0.y));
    }
    for (int it = t; it < NE * FEAT; it += BLK) {
        int n = it >> 6, f = it & 63;
        S.h[it] = emb_ee[(n < 15 ? 0 : FEAT) + f];
    }
    __syncthreads();

    for (int l = 0; l < NL; l++) {
        // gather: warps 0-14, 2 nodes each
        if (warp < 15) {
            const int n0 = 2 * warp, n1 = n0 + 1;
            const int Bn0 = ((n0 * (2 * NE - 1 - n0)) >> 1) - n0 - 1;
            const int Bn1 = ((n1 * (2 * NE - 1 - n1)) >> 1) - n1 - 1;
            u64 a0a = 0, a0b = 0, a1a = 0, a1b = 0;
            #pragma unroll
            for (int j = 0; j < NE; j++) {
                const int K1 = ((j * (2 * NE - 1 - j)) >> 1) - j - 1;
                u64 hv = *(const u64*)&S.h[j * FEAT + 2 * fp];
                if (j != n0) {
                    int p = (j < n0) ? (K1 + n0) : (Bn0 + j);
                    float2 fv = __half22float2(S.filt2[p * 32 + fp]);
                    u64 f2 = pack2(fv.x, fv.y);
                    if (j & 1) { FMA2(a0b, hv, f2, a0b); } else { FMA2(a0a, hv, f2, a0a); }
                }
                if (j != n1) {
                    int p = (j < n1) ? (K1 + n1) : (Bn1 + j);
                    float2 fv = __half22float2(S.filt2[p * 32 + fp]);
                    u64 f2 = pack2(fv.x, fv.y);
                    if (j & 1) { FMA2(a1b, hv, f2, a1b); } else { FMA2(a1a, hv, f2, a1a); }
                }
            }
            ADD2(a0a, a0a, a0b);
            ADD2(a1a, a1a, a1b);
            *(u64*)&S.agg[n0 * FEAT + 2 * fp] = a0a;
            *(u64*)&S.agg[n1 * FEAT + 2 * fp] = a1a;
        }
        __syncthreads();
        if (warp < 15) linearN(S, l, 2 * warp, 2, fp);
        __syncthreads();
    }
    float acc = 0.f;
    for (int it = t; it < NE * FEAT; it += BLK) acc = fmaf(S.h[it], S.wr[it & 63], acc);
    float k_ee = block_reduce(acc, S.red, t) + br_ee[0];

    // ================= EN graph =================
    for (int q = t; q < NPN; q += BLK) {
        int a = q / NE, e = q % NE;
        float dx = S.xyz[e * 3 + 0] - S.atm[a * 3 + 0];
        float dy = S.xyz[e * 3 + 1] - S.atm[a * 3 + 1];
        float dz = S.xyz[e * 3 + 2] - S.atm[a * 3 + 2];
        Sd[q] = sqrtf(dx * dx + dy * dy + dz * dz);
    }
    stage_weights(S, wl_en, bl_en, wr_en, t);
    __syncthreads();

    for (int it = t; it < NPN * 32; it += BLK) {
        int q = it >> 5, f2 = it & 31;
        float u = fminf(Sd[q] * INV_STEP, (float)(T_TAB - 2) + 0.999f);
        int idx = (int)u;
        float w = u - (float)idx;
        float2 v0 = *(const float2*)&g_tab_en[idx * FEAT + 2 * f2];
        float2 v1 = *(const float2*)&g_tab_en[(idx + 1) * FEAT + 2 * f2];
        S.filt2[it] = __floats2half2_rn(fmaf(w, v1.x - v0.x, v0.x),
                                        fmaf(w, v1.y - v0.y, v0.y));
    }
    for (int it = t; it < NN * FEAT; it += BLK) {
        int n = it >> 6, f = it & 63;
        int ty = (n < 15) ? 0 : (n < NE ? 1 : 2 + (n - NE));
        S.h[it] = emb_en[ty * FEAT + f];
    }
    __syncthreads();

    int en_n0, en_cnt; bool en_atom;
    en_map(warp, en_n0, en_cnt, en_atom);

    for (int l = 0; l < NL; l++) {
        // gather: all 16 warps
        {
            u64 acc[3] = {0, 0, 0};
            if (!en_atom) {  // electron nodes: neighbors = all atoms
                #pragma unroll
                for (int aa = 0; aa < NA; aa++) {
                    u64 hv = *(const u64*)&S.h[(NE + aa) * FEAT + 2 * fp];
                    #pragma unroll
                    for (int s = 0; s < 3; s++) {
                        if (s < en_cnt) {
                            float2 fv = __half22float2(
                                S.filt2[(aa * NE + en_n0 + s) * 32 + fp]);
                            u64 f2 = pack2(fv.x, fv.y);
                            FMA2(acc[s], hv, f2, acc[s]);
                        }
                    }
                }
            } else {         // atom nodes: neighbors = all electrons
                const int a0 = en_n0 - NE, a1 = a0 + 1;
                u64 b0 = 0, b1 = 0;
                #pragma unroll
                for (int e = 0; e < NE; e++) {
                    u64 hv = *(const u64*)&S.h[e * FEAT + 2 * fp];
                    float2 f0 = __half22float2(S.filt2[(a0 * NE + e) * 32 + fp]);
                    float2 f1 = __half22float2(S.filt2[(a1 * NE + e) * 32 + fp]);
                    u64 p0 = pack2(f0.x, f0.y), p1 = pack2(f1.x, f1.y);
                    if (e & 1) { FMA2(b0, hv, p0, b0); FMA2(b1, hv, p1, b1); }
                    else       { FMA2(acc[0], hv, p0, acc[0]); FMA2(acc[1], hv, p1, acc[1]); }
                }
                ADD2(acc[0], acc[0], b0);
                ADD2(acc[1], acc[1], b1);
            }
            #pragma unroll
            for (int s = 0; s < 3; s++)
                if (s < en_cnt) *(u64*)&S.agg[(en_n0 + s) * FEAT + 2 * fp] = acc[s];
        }
        __syncthreads();
        linearN(S, l, en_n0, en_cnt, fp);
        __syncthreads();
    }
    float acc2 = 0.f;
    for (int it = t; it < NN * FEAT; it += BLK) acc2 = fmaf(S.h[it], S.wr[it & 63], acc2);
    float k_en = block_reduce(acc2, S.red, t) + br_en[0];

    if (t == 0) out[b] = expf(k_ee + k_en);
}

// ---------------------------------------------------------------------------
extern "C" void kernel_launch(void* const* d_in, const int* in_sizes, int n_in,
                              void* d_out, int out_size) {
    const float* pos    = (const float*)d_in[0];
    const float* atoms  = (const float*)d_in[1];
    const float* emb_ee = (const float*)d_in[2];
    const float* wf_ee  = (const float*)d_in[3];
    const float* bf_ee  = (const float*)d_in[4];
    const float* wl_ee  = (const float*)d_in[5];
    const float* bl_ee  = (const float*)d_in[6];
    const float* wr_ee  = (const float*)d_in[7];
    const float* br_ee  = (const float*)d_in[8];
    const float* emb_en = (const float*)d_in[9];
    const float* wf_en  = (const float*)d_in[10];
    const float* bf_en  = (const float*)d_in[11];
    const float* wl_en  = (const float*)d_in[12];
    const float* bl_en  = (const float*)d_in[13];
    const float* wr_en  = (const float*)d_in[14];
    const float* br_en  = (const float*)d_in[15];
    float* out = (float*)d_out;

    int nb = in_sizes[0] / (NE * 3);

    cudaFuncSetAttribute(jastrow_kernel,
                         cudaFuncAttributeMaxDynamicSharedMemorySize,
                         (int)sizeof(Smem));

    build_tab_kernel<<<dim3(T_TAB / 8, 2), 256>>>(wf_ee, bf_ee, wf_en, bf_en);
    jastrow_kernel<<<nb, BLK, sizeof(Smem)>>>(
        pos, atoms, emb_ee, wl_ee, bl_ee, wr_ee, br_ee,
        emb_en, wl_en, bl_en, wr_en, br_en, out);
}